// round 10
// baseline (speedup 1.0000x reference)
#include <cuda_runtime.h>
#include <cstdint>

// Problem constants
#define BB   128        // batch
#define IN_  1024
#define OUT_ 1024
#define NS   16         // i-dimension splits (empirical optimum)
#define LI   (IN_/NS)   // 64 i-values per split
#define NB   8          // batches per block (amortization sweet spot)
#define NBG  (BB/NB)    // 16 batch groups
#define OT   256        // outs per block
#define OTG  (OUT_/OT)  // 4 out groups
#define O4   (OUT_/4)   // 256 float4 lanes over full OUT
#define OT4  (OT/4)     // 64 float4 lanes per block

// Scratch (allocation-free rule: __device__ global)
// TRANSPOSED partial layout: g_partial[(b*O4 + oc) * NS + s] as float4 —
// the 16 s-partials of one output float4 are 256 contiguous bytes, so the
// reduce kernel streams sequentially instead of striding 512 KB.
__device__ float4 g_partial[BB * O4 * NS];    // 8 MB

// ---------------------------------------------------------------------------
// Main streaming kernel — proven-fastest loop: 1024 blocks of 128 threads,
// occ 7. Block (s,bg,z): i in [s*LI,(s+1)*LI), batches [bg*8,bg*8+8),
// outs [z*256,z*256+256). acc[4] float4/thread. x staged via 2KB smem.
// softplus(ro) fused; bias folded into s==0 partials; eps via __ldcs.
// Only the epilogue changed vs R9: partials stored transposed.
// ---------------------------------------------------------------------------
__global__ __launch_bounds__(128, 7)
void main_kernel(const float* __restrict__ x,
                 const float* __restrict__ mu,
                 const float* __restrict__ ro,
                 const float* __restrict__ eps,
                 const float* __restrict__ mu_bias,
                 const float* __restrict__ ro_bias,
                 const float* __restrict__ eps_bias) {
    __shared__ float xs[NB][LI];          // 2 KB

    const int bx = blockIdx.x;            // 0..1023
    const int s  = bx & (NS - 1);         // 0..15
    const int bg = (bx >> 4) & (NBG - 1); // 0..15
    const int z  = bx >> 8;               // 0..3
    const int t  = threadIdx.x;
    const int l  = t & (OT4 - 1);         // o float4 lane (0..63)
    const int g  = t >> 6;                // 0..1 batch class
    const int i0 = s * LI;
    const int b0 = bg * NB;
    const int oc = z * OT4 + l;           // float4 column in [0, O4)

    // Cooperative float4 load of x tile [8 b][64 i]: 128 float4s, one each
    {
        const int row = t >> 4;           // 0..7
        const int col = (t & 15) * 4;     // 0..60
        float4 v = *reinterpret_cast<const float4*>(
            x + (size_t)(b0 + row) * IN_ + i0 + col);
        *reinterpret_cast<float4*>(&xs[row][col]) = v;
    }
    __syncthreads();

    const float4* mu4 = reinterpret_cast<const float4*>(mu)  + (size_t)i0 * O4 + oc;
    const float4* ro4 = reinterpret_cast<const float4*>(ro)  + (size_t)i0 * O4 + oc;
    const float4* ep4 = reinterpret_cast<const float4*>(eps)
                        + ((size_t)b0 * IN_ + i0) * O4 + oc;

    float4 acc[4];

    // ---- ii = 0 peeled: pure multiply (initializes acc) ----
    {
        float4 ev[4];
#pragma unroll
        for (int k = 0; k < 4; k++) {
            const int lb = g + 2 * k;
            ev[k] = __ldcs(&ep4[(size_t)lb * IN_ * O4]);
        }
        const float4 rr = ro4[0];
        const float4 mw = mu4[0];
        float4 sg;
        sg.x = log1pf(__expf(rr.x));
        sg.y = log1pf(__expf(rr.y));
        sg.z = log1pf(__expf(rr.z));
        sg.w = log1pf(__expf(rr.w));
#pragma unroll
        for (int k = 0; k < 4; k++) {
            const int lb = g + 2 * k;
            const float xr = xs[lb][0];
            acc[k].x = xr * fmaf(ev[k].x, sg.x, mw.x);
            acc[k].y = xr * fmaf(ev[k].y, sg.y, mw.y);
            acc[k].z = xr * fmaf(ev[k].z, sg.z, mw.z);
            acc[k].w = xr * fmaf(ev[k].w, sg.w, mw.w);
        }
    }

    // ---- ii = 1 .. LI-1 ----
#pragma unroll 1
    for (int ii = 1; ii < LI; ii++) {
        float4 ev[4];
#pragma unroll
        for (int k = 0; k < 4; k++) {
            const int lb = g + 2 * k;
            ev[k] = __ldcs(&ep4[((size_t)lb * IN_ + ii) * O4]);
        }
        const float4 rr = ro4[(size_t)ii * O4];
        const float4 mw = mu4[(size_t)ii * O4];
        float4 sg;
        sg.x = log1pf(__expf(rr.x));
        sg.y = log1pf(__expf(rr.y));
        sg.z = log1pf(__expf(rr.z));
        sg.w = log1pf(__expf(rr.w));
#pragma unroll
        for (int k = 0; k < 4; k++) {
            const int lb = g + 2 * k;
            const float xr = xs[lb][ii];
            acc[k].x = fmaf(xr, fmaf(ev[k].x, sg.x, mw.x), acc[k].x);
            acc[k].y = fmaf(xr, fmaf(ev[k].y, sg.y, mw.y), acc[k].y);
            acc[k].z = fmaf(xr, fmaf(ev[k].z, sg.z, mw.z), acc[k].z);
            acc[k].w = fmaf(xr, fmaf(ev[k].w, sg.w, mw.w), acc[k].w);
        }
    }

    // ---- s==0 blocks fold in the bias term ----
    if (s == 0) {
        const float4 rb = reinterpret_cast<const float4*>(ro_bias)[oc];
        const float4 mb = reinterpret_cast<const float4*>(mu_bias)[oc];
        float4 sb;
        sb.x = log1pf(__expf(rb.x));
        sb.y = log1pf(__expf(rb.y));
        sb.z = log1pf(__expf(rb.z));
        sb.w = log1pf(__expf(rb.w));
#pragma unroll
        for (int k = 0; k < 4; k++) {
            const int lb = g + 2 * k;
            const float4 eb = reinterpret_cast<const float4*>(eps_bias)
                                  [(size_t)(b0 + lb) * O4 + oc];
            acc[k].x = fmaf(eb.x, sb.x, acc[k].x + mb.x);
            acc[k].y = fmaf(eb.y, sb.y, acc[k].y + mb.y);
            acc[k].z = fmaf(eb.z, sb.z, acc[k].z + mb.z);
            acc[k].w = fmaf(eb.w, sb.w, acc[k].w + mb.w);
        }
    }

    // ---- write partials (transposed): P[(b*O4 + oc)*NS + s] ----
#pragma unroll
    for (int k = 0; k < 4; k++) {
        const int lb = g + 2 * k;
        g_partial[((size_t)(b0 + lb) * O4 + oc) * NS + s] = acc[k];
    }
}

// ---------------------------------------------------------------------------
// Reduce over s, transposed layout. Warp = 8 output float4s x 4 lanes; lane
// q sums float4s [4q, 4q+4) of its pair (contiguous 64 B), then a fixed-tree
// shfl_xor combine: (q0+q1)+(q2+q3) — deterministic regardless of timing.
// Each warp reads 2 KB fully contiguous; 8 MB total streams at DRAM/L2 rate.
// ---------------------------------------------------------------------------
__global__ __launch_bounds__(128)
void reduce_kernel(float* __restrict__ out) {
    const int t    = threadIdx.x;
    const int q    = t & 3;                             // 0..3 quarter
    const int pair = (blockIdx.x * 128 + t) >> 2;       // 0..BB*O4-1

    const float4* Pc = g_partial + (size_t)pair * NS + q * 4;

    // Fixed ascending order within quarter
    float4 r = Pc[0];
#pragma unroll
    for (int j = 1; j < 4; j++) {
        float4 p = Pc[j];
        r.x += p.x; r.y += p.y; r.z += p.z; r.w += p.w;
    }

    // Fixed-tree combine across the 4 lanes of this pair: (q0+q1)+(q2+q3)
#pragma unroll
    for (int d = 1; d < 4; d <<= 1) {
        r.x += __shfl_xor_sync(0xFFFFFFFFu, r.x, d);
        r.y += __shfl_xor_sync(0xFFFFFFFFu, r.y, d);
        r.z += __shfl_xor_sync(0xFFFFFFFFu, r.z, d);
        r.w += __shfl_xor_sync(0xFFFFFFFFu, r.w, d);
    }

    if (q == 0)
        reinterpret_cast<float4*>(out)[pair] = r;
}

// ---------------------------------------------------------------------------
// Launch. Input order (metadata): x, mu, ro, mu_bias, ro_bias, eps, eps_bias
// ---------------------------------------------------------------------------
extern "C" void kernel_launch(void* const* d_in, const int* in_sizes, int n_in,
                              void* d_out, int out_size) {
    const float* x        = (const float*)d_in[0];
    const float* mu       = (const float*)d_in[1];
    const float* ro       = (const float*)d_in[2];
    const float* mu_bias  = (const float*)d_in[3];
    const float* ro_bias  = (const float*)d_in[4];
    const float* eps      = (const float*)d_in[5];
    const float* eps_bias = (const float*)d_in[6];
    float* out = (float*)d_out;

    // Main: 1024 blocks x 128 threads, occ 7 (proven fastest streaming loop)
    main_kernel<<<NS * NBG * OTG, 128>>>(x, mu, ro, eps,
                                         mu_bias, ro_bias, eps_bias);

    // Reduce: BB*O4 pairs x 4 lanes = 131072 threads
    reduce_kernel<<<(BB * O4 * 4) / 128, 128>>>(out);
}

// round 11
// speedup vs baseline: 1.0213x; 1.0213x over previous
#include <cuda_runtime.h>
#include <cstdint>

// Problem constants
#define BB   128        // batch
#define IN_  1024
#define OUT_ 1024
#define NS   16         // i-dimension splits (empirical optimum)
#define LI   (IN_/NS)   // 64 i-values per split
#define NB   8          // batches per block (amortization sweet spot)
#define NBG  (BB/NB)    // 16 batch groups
#define OT   256        // outs per block
#define OTG  (OUT_/OT)  // 4 out groups
#define O4   (OUT_/4)   // 256 float4 lanes over full OUT
#define OT4  (OT/4)     // 64 float4 lanes per block

// Scratch (allocation-free rule: __device__ global)
__device__ float g_partial[NS * BB * OUT_];   // per-split partials, 8 MB

// ---------------------------------------------------------------------------
// Main streaming kernel — R9's proven-fastest config (main ~81us): 1024
// blocks of 128 threads, occ 7. Block (s,bg,z): i in [s*LI,(s+1)*LI),
// batches [bg*8,bg*8+8), outs [z*256,z*256+256). acc[4] float4/thread.
// x staged via 2KB smem. softplus(ro) fused; bias folded into s==0 partials;
// eps via __ldcs (evict-first). Partials stored in coalesced [s][b][o]
// layout (transposed layout measured WORSE in R10: scattered stores cost
// ~2us and the reduce did not speed up — its 5.5us is launch-floor, not
// memory pattern). PDL trigger at block end lets the reduce kernel's launch
// overhead overlap this kernel's execution.
// ---------------------------------------------------------------------------
__global__ __launch_bounds__(128, 7)
void main_kernel(const float* __restrict__ x,
                 const float* __restrict__ mu,
                 const float* __restrict__ ro,
                 const float* __restrict__ eps,
                 const float* __restrict__ mu_bias,
                 const float* __restrict__ ro_bias,
                 const float* __restrict__ eps_bias) {
    __shared__ float xs[NB][LI];          // 2 KB

    const int bx = blockIdx.x;            // 0..1023
    const int s  = bx & (NS - 1);         // 0..15
    const int bg = (bx >> 4) & (NBG - 1); // 0..15
    const int z  = bx >> 8;               // 0..3
    const int t  = threadIdx.x;
    const int l  = t & (OT4 - 1);         // o float4 lane (0..63)
    const int g  = t >> 6;                // 0..1 batch class
    const int i0 = s * LI;
    const int b0 = bg * NB;
    const int oc = z * OT4 + l;           // float4 column in [0, O4)

    // Cooperative float4 load of x tile [8 b][64 i]: 128 float4s, one each
    {
        const int row = t >> 4;           // 0..7
        const int col = (t & 15) * 4;     // 0..60
        float4 v = *reinterpret_cast<const float4*>(
            x + (size_t)(b0 + row) * IN_ + i0 + col);
        *reinterpret_cast<float4*>(&xs[row][col]) = v;
    }
    __syncthreads();

    const float4* mu4 = reinterpret_cast<const float4*>(mu)  + (size_t)i0 * O4 + oc;
    const float4* ro4 = reinterpret_cast<const float4*>(ro)  + (size_t)i0 * O4 + oc;
    const float4* ep4 = reinterpret_cast<const float4*>(eps)
                        + ((size_t)b0 * IN_ + i0) * O4 + oc;

    float4 acc[4];

    // ---- ii = 0 peeled: pure multiply (initializes acc) ----
    {
        float4 ev[4];
#pragma unroll
        for (int k = 0; k < 4; k++) {
            const int lb = g + 2 * k;
            ev[k] = __ldcs(&ep4[(size_t)lb * IN_ * O4]);
        }
        const float4 rr = ro4[0];
        const float4 mw = mu4[0];
        float4 sg;
        sg.x = log1pf(__expf(rr.x));
        sg.y = log1pf(__expf(rr.y));
        sg.z = log1pf(__expf(rr.z));
        sg.w = log1pf(__expf(rr.w));
#pragma unroll
        for (int k = 0; k < 4; k++) {
            const int lb = g + 2 * k;
            const float xr = xs[lb][0];
            acc[k].x = xr * fmaf(ev[k].x, sg.x, mw.x);
            acc[k].y = xr * fmaf(ev[k].y, sg.y, mw.y);
            acc[k].z = xr * fmaf(ev[k].z, sg.z, mw.z);
            acc[k].w = xr * fmaf(ev[k].w, sg.w, mw.w);
        }
    }

    // ---- ii = 1 .. LI-1 ----
#pragma unroll 1
    for (int ii = 1; ii < LI; ii++) {
        float4 ev[4];
#pragma unroll
        for (int k = 0; k < 4; k++) {
            const int lb = g + 2 * k;
            ev[k] = __ldcs(&ep4[((size_t)lb * IN_ + ii) * O4]);
        }
        const float4 rr = ro4[(size_t)ii * O4];
        const float4 mw = mu4[(size_t)ii * O4];
        float4 sg;
        sg.x = log1pf(__expf(rr.x));
        sg.y = log1pf(__expf(rr.y));
        sg.z = log1pf(__expf(rr.z));
        sg.w = log1pf(__expf(rr.w));
#pragma unroll
        for (int k = 0; k < 4; k++) {
            const int lb = g + 2 * k;
            const float xr = xs[lb][ii];
            acc[k].x = fmaf(xr, fmaf(ev[k].x, sg.x, mw.x), acc[k].x);
            acc[k].y = fmaf(xr, fmaf(ev[k].y, sg.y, mw.y), acc[k].y);
            acc[k].z = fmaf(xr, fmaf(ev[k].z, sg.z, mw.z), acc[k].z);
            acc[k].w = fmaf(xr, fmaf(ev[k].w, sg.w, mw.w), acc[k].w);
        }
    }

    // ---- s==0 blocks fold in the bias term ----
    if (s == 0) {
        const float4 rb = reinterpret_cast<const float4*>(ro_bias)[oc];
        const float4 mb = reinterpret_cast<const float4*>(mu_bias)[oc];
        float4 sb;
        sb.x = log1pf(__expf(rb.x));
        sb.y = log1pf(__expf(rb.y));
        sb.z = log1pf(__expf(rb.z));
        sb.w = log1pf(__expf(rb.w));
#pragma unroll
        for (int k = 0; k < 4; k++) {
            const int lb = g + 2 * k;
            const float4 eb = reinterpret_cast<const float4*>(eps_bias)
                                  [(size_t)(b0 + lb) * O4 + oc];
            acc[k].x = fmaf(eb.x, sb.x, acc[k].x + mb.x);
            acc[k].y = fmaf(eb.y, sb.y, acc[k].y + mb.y);
            acc[k].z = fmaf(eb.z, sb.z, acc[k].z + mb.z);
            acc[k].w = fmaf(eb.w, sb.w, acc[k].w + mb.w);
        }
    }

    // ---- write partials P[s][b][o] (coalesced) ----
    float4* Pbase = reinterpret_cast<float4*>(g_partial);
#pragma unroll
    for (int k = 0; k < 4; k++) {
        const int lb = g + 2 * k;
        Pbase[((size_t)s * BB + b0 + lb) * O4 + oc] = acc[k];
    }

    // PDL: signal completion (fires once all blocks reach here; lets the
    // dependent reduce kernel proceed past its grid-dependency sync).
    cudaTriggerProgrammaticLaunchCompletion();
}

// ---------------------------------------------------------------------------
// Reduce: 4-way-split s-sum (R9 structure, measured best among variants).
// Launched with PDL so its ~4us launch/ramp floor overlaps the main kernel;
// cudaGridDependencySynchronize() gates the actual partial reads.
// Thread (q=t>>5, lane=t&31) sums partials s in [4q,4q+4) for output lane
// L, quarters combine via smem in fixed q-order (deterministic).
// ---------------------------------------------------------------------------
__global__ __launch_bounds__(128)
void reduce_kernel(float* __restrict__ out) {
    __shared__ float4 red[4][32];

    // Overlap window: everything above this line (scheduling, prologue)
    // runs while main_kernel is still executing.
    cudaGridDependencySynchronize();

    const int t    = threadIdx.x;
    const int lane = t & 31;
    const int q    = t >> 5;                       // 0..3
    const int L    = blockIdx.x * 32 + lane;       // 0..BB*O4-1

    const float4* Pc = reinterpret_cast<const float4*>(g_partial) + L;

    // Fixed ascending order within quarter
    float4 r = Pc[(size_t)(q * 4) * BB * O4];
#pragma unroll
    for (int j = 1; j < 4; j++) {
        float4 p = Pc[(size_t)(q * 4 + j) * BB * O4];
        r.x += p.x; r.y += p.y; r.z += p.z; r.w += p.w;
    }
    red[q][lane] = r;
    __syncthreads();

    if (q == 0) {
        // Fixed quarter order -> deterministic
        float4 a = red[0][lane];
#pragma unroll
        for (int j = 1; j < 4; j++) {
            float4 p = red[j][lane];
            a.x += p.x; a.y += p.y; a.z += p.z; a.w += p.w;
        }
        reinterpret_cast<float4*>(out)[L] = a;
    }
}

// ---------------------------------------------------------------------------
// Launch. Input order (metadata): x, mu, ro, mu_bias, ro_bias, eps, eps_bias
// ---------------------------------------------------------------------------
extern "C" void kernel_launch(void* const* d_in, const int* in_sizes, int n_in,
                              void* d_out, int out_size) {
    const float* x        = (const float*)d_in[0];
    const float* mu       = (const float*)d_in[1];
    const float* ro       = (const float*)d_in[2];
    const float* mu_bias  = (const float*)d_in[3];
    const float* ro_bias  = (const float*)d_in[4];
    const float* eps      = (const float*)d_in[5];
    const float* eps_bias = (const float*)d_in[6];
    float* out = (float*)d_out;

    // Main: 1024 blocks x 128 threads, occ 7 (proven fastest streaming loop)
    main_kernel<<<NS * NBG * OTG, 128>>>(x, mu, ro, eps,
                                         mu_bias, ro_bias, eps_bias);

    // Reduce with Programmatic Dependent Launch: launch overhead overlaps
    // the main kernel; the grid-dependency sync inside gates data reads.
    cudaLaunchConfig_t cfg = {};
    cfg.gridDim  = dim3((BB * O4) / 32);
    cfg.blockDim = dim3(128);
    cfg.dynamicSmemBytes = 0;
    cfg.stream = 0;   // legacy default stream (same as <<< >>> above)
    cudaLaunchAttribute attrs[1];
    attrs[0].id = cudaLaunchAttributeProgrammaticStreamSerialization;
    attrs[0].val.programmaticStreamSerializationAllowed = 1;
    cfg.attrs = attrs;
    cfg.numAttrs = 1;
    cudaLaunchKernelEx(&cfg, reduce_kernel, out);
}